// round 9
// baseline (speedup 1.0000x reference)
#include <cuda_runtime.h>
#include <cuda_bf16.h>
#include <cuda_fp16.h>
#include <math.h>
#include <stdint.h>

// Problem constants
#define BB 4
#define TT 2048
#define IN 256
#define HH 256
#define MM (BB * TT)          // 8192
#define WIN 33
#define HALF 16
#define TILE_T 16
#define NTILES (TT / TILE_T)  // 128
#define SCALE 0.0625f
#define EPS 1e-5f

// GEMM tiling: CTA 128x64, BK=32 (2 k16 steps), warp tile 32x32.
#define BM 128
#define BN 64
#define BK 32
// Stage layout (u32 units). Per row: 16 slots x (h,l) = 32 u32 data + 8 pad = 40.
//   addr(row, kstep, pair, hl) = row*40 + kstep*16 + pair*2 + hl
#define S_ROW 40
#define A_REG (BM * S_ROW)            // 5120
#define B_REG (BN * S_ROW)            // 2560
#define STAGE_U32 (A_REG + B_REG)     // 7680 u32 = 30 KB

// Scratch (device globals: allowed)
__device__ float g_y[3][MM * HH];
__device__ float g_statp[3][MM / BM][HH][2];   // per (s, m-block, col): sum, sumsq
__device__ float g_mean[3][BB * HH];
__device__ float g_rstd[3][BB * HH];
__device__ float g_partial[BB * NTILES * HH];
__device__ float g_partial2[BB * 16 * HH];

__device__ __forceinline__ void mma_f16(float c[4], const unsigned a[4], const unsigned b[2]) {
    asm volatile(
        "mma.sync.aligned.m16n8k16.row.col.f32.f16.f16.f32 "
        "{%0,%1,%2,%3}, {%4,%5,%6,%7}, {%8,%9}, {%0,%1,%2,%3};"
        : "+f"(c[0]), "+f"(c[1]), "+f"(c[2]), "+f"(c[3])
        : "r"(a[0]), "r"(a[1]), "r"(a[2]), "r"(a[3]), "r"(b[0]), "r"(b[1]));
}

// Dummy kernel: positions the ATTN kernel in ncu's profiled (4th) launch slot.
__global__ void noop_kernel() {}

// ---------------------------------------------------------------------------
// Kernel 1: y[s] = x @ W[s].T + b[s] via 2-term fp16 split (hi+lo), k16 MMA.
// (h,l) adjacent in smem: staging = 6 conflict-free STS.128/thread/kt;
// fragment loads = LDS.64 fetching h+l together, 16-lane bank bijection.
// Double-buffered. Epilogue emits per-block column (sum,sumsq) stat partials.
// ---------------------------------------------------------------------------
__global__ __launch_bounds__(256, 2) void gemm_qkv_kernel(
    const float* __restrict__ x,
    const float* __restrict__ Wq, const float* __restrict__ bq,
    const float* __restrict__ Wk, const float* __restrict__ bk,
    const float* __restrict__ Wv, const float* __restrict__ bv)
{
    const int s = blockIdx.z;
    const float* W    = (s == 0) ? Wq : (s == 1) ? Wk : Wv;
    const float* bias = (s == 0) ? bq : (s == 1) ? bk : bv;
    float* y = g_y[s];

    extern __shared__ uint32_t smu[];   // 2 stages of STAGE_U32

    const int m0  = blockIdx.x * BM;
    const int n0  = blockIdx.y * BN;
    const int tid = threadIdx.x;
    const int wid = tid >> 5;
    const int lane = tid & 31;
    const int rb0 = (wid >> 1) * 2;   // A 16-row block base
    const int nb0 = (wid & 1) * 4;    // B 8-row block base
    const int gr = lane >> 2;         // 0..7
    const int gc = lane & 3;          // 0..3

    float acc[2][4][4] = {};

    // split float4 -> packed {h01, l01, h23, l23} single STS.128
    auto split_store = [](uint32_t* dst, float4 f) {
        __half2 h01 = __floats2half2_rn(f.x, f.y);
        __half2 h23 = __floats2half2_rn(f.z, f.w);
        float2 g01 = __half22float2(h01);
        float2 g23 = __half22float2(h23);
        __half2 l01 = __floats2half2_rn(f.x - g01.x, f.y - g01.y);
        __half2 l23 = __floats2half2_rn(f.z - g23.x, f.w - g23.y);
        uint4 u;
        u.x = *(unsigned*)&h01; u.y = *(unsigned*)&l01;
        u.z = *(unsigned*)&h23; u.w = *(unsigned*)&l23;
        *(uint4*)dst = u;
    };

    auto store_stage = [&](uint32_t* st, const float4 xa[4], const float4 wb[2]) {
        #pragma unroll
        for (int j = 0; j < 4; j++) {
            int idx = tid + j * 256;
            int row = idx >> 3, kc = (idx & 7) << 2;
            int kstep = kc >> 4, lp0 = (kc & 15) >> 1;   // 0,2,4,6
            split_store(st + row * S_ROW + kstep * 16 + lp0 * 2, xa[j]);
        }
        #pragma unroll
        for (int j = 0; j < 2; j++) {
            int idx = tid + j * 256;
            int n = idx >> 3, kc = (idx & 7) << 2;
            int kstep = kc >> 4, lp0 = (kc & 15) >> 1;
            split_store(st + A_REG + n * S_ROW + kstep * 16 + lp0 * 2, wb[j]);
        }
    };
    auto fetch = [&](float4 xa[4], float4 wb[2], int k0) {
        #pragma unroll
        for (int j = 0; j < 4; j++) {
            int idx = tid + j * 256;
            int r = idx >> 3, kp = (idx & 7) << 2;
            xa[j] = *(const float4*)&x[(size_t)(m0 + r) * IN + k0 + kp];
        }
        #pragma unroll
        for (int j = 0; j < 2; j++) {
            int idx = tid + j * 256;
            int r = idx >> 3, kp = (idx & 7) << 2;
            wb[j] = *(const float4*)&W[(size_t)(n0 + r) * IN + k0 + kp];
        }
    };

    // Prologue: chunk0 -> buf0; prefetch chunk1.
    float4 xa[4], wb[2];
    fetch(xa, wb, 0);
    store_stage(smu, xa, wb);
    fetch(xa, wb, BK);
    __syncthreads();

    #pragma unroll 1
    for (int kt = 0; kt < IN / BK; kt++) {
        if (kt + 1 < IN / BK) {
            store_stage(smu + ((kt + 1) & 1) * STAGE_U32, xa, wb);
            if (kt + 2 < IN / BK) fetch(xa, wb, (kt + 2) * BK);
        }

        const uint32_t* st = smu + (kt & 1) * STAGE_U32;
        const uint32_t* Bst = st + A_REG;

        #pragma unroll
        for (int ks2 = 0; ks2 < 2; ks2++) {
            const int kb = ks2 * 16;
            unsigned ah[2][4], al[2][4], bh[4][2], bl[4][2];
            #pragma unroll
            for (int mi = 0; mi < 2; mi++) {
                int r0 = ((rb0 + mi) * 16 + gr) * S_ROW + kb;
                uint2 p0 = *(const uint2*)&st[r0 + 2 * gc];
                uint2 p1 = *(const uint2*)&st[r0 + 8 * S_ROW + 2 * gc];
                uint2 p2 = *(const uint2*)&st[r0 + 2 * (gc + 4)];
                uint2 p3 = *(const uint2*)&st[r0 + 8 * S_ROW + 2 * (gc + 4)];
                ah[mi][0] = p0.x; al[mi][0] = p0.y;
                ah[mi][1] = p1.x; al[mi][1] = p1.y;
                ah[mi][2] = p2.x; al[mi][2] = p2.y;
                ah[mi][3] = p3.x; al[mi][3] = p3.y;
            }
            #pragma unroll
            for (int ni = 0; ni < 4; ni++) {
                int nr = ((nb0 + ni) * 8 + gr) * S_ROW + kb;
                uint2 q0 = *(const uint2*)&Bst[nr + 2 * gc];
                uint2 q1 = *(const uint2*)&Bst[nr + 2 * (gc + 4)];
                bh[ni][0] = q0.x; bl[ni][0] = q0.y;
                bh[ni][1] = q1.x; bl[ni][1] = q1.y;
            }
            #pragma unroll
            for (int mi = 0; mi < 2; mi++)
                #pragma unroll
                for (int ni = 0; ni < 4; ni++) {
                    mma_f16(acc[mi][ni], ah[mi], bl[ni]);
                    mma_f16(acc[mi][ni], al[mi], bh[ni]);
                    mma_f16(acc[mi][ni], ah[mi], bh[ni]);
                }
        }
        __syncthreads();
    }

    // ---- Epilogue: bias + store + per-column stat partials ----
    const int wm = rb0 * 16;
    const int wn = nb0 * 8;
    float scol[8], qcol[8];
    #pragma unroll
    for (int ni = 0; ni < 4; ni++) {
        int col = n0 + wn + ni * 8 + 2 * gc;
        float b0 = bias[col], b1 = bias[col + 1];
        float ss0 = 0.f, ss1 = 0.f, qq0 = 0.f, qq1 = 0.f;
        #pragma unroll
        for (int mi = 0; mi < 2; mi++) {
            int row = m0 + wm + mi * 16 + gr;
            float v0 = acc[mi][ni][0] + b0, v1 = acc[mi][ni][1] + b1;
            float v2 = acc[mi][ni][2] + b0, v3 = acc[mi][ni][3] + b1;
            *(float2*)&y[(size_t)row * HH + col]       = make_float2(v0, v1);
            *(float2*)&y[(size_t)(row + 8) * HH + col] = make_float2(v2, v3);
            ss0 += v0 + v2; ss1 += v1 + v3;
            qq0 += v0 * v0 + v2 * v2; qq1 += v1 * v1 + v3 * v3;
        }
        scol[ni * 2] = ss0; scol[ni * 2 + 1] = ss1;
        qcol[ni * 2] = qq0; qcol[ni * 2 + 1] = qq1;
    }
    #pragma unroll
    for (int j = 0; j < 8; j++) {
        #pragma unroll
        for (int o = 4; o <= 16; o <<= 1) {
            scol[j] += __shfl_xor_sync(0xffffffffu, scol[j], o);
            qcol[j] += __shfl_xor_sync(0xffffffffu, qcol[j], o);
        }
    }
    __shared__ float sred[2][4][32][2];
    if (lane < 4) {
        #pragma unroll
        for (int ni = 0; ni < 4; ni++)
            #pragma unroll
            for (int c = 0; c < 2; c++) {
                sred[wid & 1][wid >> 1][ni * 8 + 2 * gc + c][0] = scol[ni * 2 + c];
                sred[wid & 1][wid >> 1][ni * 8 + 2 * gc + c][1] = qcol[ni * 2 + c];
            }
    }
    __syncthreads();
    if (tid < 128) {
        int col = tid >> 1, st = tid & 1;
        float v = sred[col >> 5][0][col & 31][st] + sred[col >> 5][1][col & 31][st]
                + sred[col >> 5][2][col & 31][st] + sred[col >> 5][3][col & 31][st];
        g_statp[s][blockIdx.x][n0 + col][st] = v;
    }
}

// ---------------------------------------------------------------------------
// Kernel 2: finalize per-(b,h) mean / rstd from GEMM partials.
// ---------------------------------------------------------------------------
__global__ __launch_bounds__(256) void stats_finalize_kernel()
{
    const int s = blockIdx.x;
    const int b = blockIdx.y;
    const int h = threadIdx.x;
    float S = 0.f, Q = 0.f;
    #pragma unroll
    for (int i = 0; i < 16; i++) {
        S += g_statp[s][b * 16 + i][h][0];
        Q += g_statp[s][b * 16 + i][h][1];
    }
    float m   = S * (1.0f / TT);
    float var = Q * (1.0f / TT) - m * m;
    g_mean[s][b * HH + h] = m;
    g_rstd[s][b * HH + h] = rsqrtf(var + EPS);
}

// ---------------------------------------------------------------------------
// Kernel 3: fused normalize + windowed attention + per-tile partial sums.
// ---------------------------------------------------------------------------
__global__ __launch_bounds__(256) void attn_kernel()
{
    extern __shared__ float sm[];
    float* k_s   = sm;                       // 48*256
    float* v_s   = sm + 48 * 256;            // 48*256
    float* sc    = sm + 96 * 256;            // 16*36
    float* coeff = sc + 16 * 36;             // 64 (48 used)
    float* st    = coeff + 64;               // 6*256
    float* mq_s = st;         float* rq_s = st + 256;
    float* mk_s = st + 512;   float* rk_s = st + 768;
    float* mv_s = st + 1024;  float* rv_s = st + 1280;

    const int tile = blockIdx.x;
    const int b    = blockIdx.y;
    const int t0   = tile * TILE_T;
    const int tid  = threadIdx.x;

    {
        int off = b * HH + tid;
        mq_s[tid] = g_mean[0][off]; rq_s[tid] = g_rstd[0][off];
        mk_s[tid] = g_mean[1][off]; rk_s[tid] = g_rstd[1][off];
        mv_s[tid] = g_mean[2][off]; rv_s[tid] = g_rstd[2][off];
    }
    __syncthreads();

    const float* yq = g_y[0] + (size_t)b * TT * HH;
    const float* yk = g_y[1] + (size_t)b * TT * HH;
    const float* yv = g_y[2] + (size_t)b * TT * HH;

    for (int i = tid; i < 48 * 64; i += 256) {
        int row = i >> 6;
        int h   = (i & 63) << 2;
        int tg  = t0 - HALF + row;
        int tc  = tg < 0 ? 0 : (tg > TT - 1 ? TT - 1 : tg);
        float4 kk = *(const float4*)&yk[(size_t)tc * HH + h];
        float4 vv = *(const float4*)&yv[(size_t)tc * HH + h];
        float4 mk = *(float4*)&mk_s[h]; float4 rk = *(float4*)&rk_s[h];
        float4 mv = *(float4*)&mv_s[h]; float4 rv = *(float4*)&rv_s[h];
        kk.x = (kk.x - mk.x) * rk.x; kk.y = (kk.y - mk.y) * rk.y;
        kk.z = (kk.z - mk.z) * rk.z; kk.w = (kk.w - mk.w) * rk.w;
        vv.x = (vv.x - mv.x) * rv.x; vv.y = (vv.y - mv.y) * rv.y;
        vv.z = (vv.z - mv.z) * rv.z; vv.w = (vv.w - mv.w) * rv.w;
        *(float4*)&k_s[row * 256 + h] = kk;
        *(float4*)&v_s[row * 256 + h] = vv;
    }
    __syncthreads();

    const int wid  = tid >> 5;
    const int lane = tid & 31;
    for (int tl = wid; tl < TILE_T; tl += 8) {
        const float* qr = &yq[(size_t)(t0 + tl) * HH];
        float4 q0 = *(const float4*)&qr[lane << 2];
        float4 q1 = *(const float4*)&qr[128 + (lane << 2)];
        float4 mq0 = *(float4*)&mq_s[lane << 2];         float4 rq0 = *(float4*)&rq_s[lane << 2];
        float4 mq1 = *(float4*)&mq_s[128 + (lane << 2)]; float4 rq1 = *(float4*)&rq_s[128 + (lane << 2)];
        q0.x = (q0.x - mq0.x) * rq0.x; q0.y = (q0.y - mq0.y) * rq0.y;
        q0.z = (q0.z - mq0.z) * rq0.z; q0.w = (q0.w - mq0.w) * rq0.w;
        q1.x = (q1.x - mq1.x) * rq1.x; q1.y = (q1.y - mq1.y) * rq1.y;
        q1.z = (q1.z - mq1.z) * rq1.z; q1.w = (q1.w - mq1.w) * rq1.w;
        int tg = t0 + tl;
        #pragma unroll 1
        for (int w = 0; w < WIN; w++) {
            const float* kr = &k_s[(tl + w) * 256];
            float4 k0 = *(float4*)&kr[lane << 2];
            float4 k1 = *(float4*)&kr[128 + (lane << 2)];
            float d = q0.x * k0.x + q0.y * k0.y + q0.z * k0.z + q0.w * k0.w
                    + q1.x * k1.x + q1.y * k1.y + q1.z * k1.z + q1.w * k1.w;
            #pragma unroll
            for (int o = 16; o; o >>= 1) d += __shfl_xor_sync(0xffffffffu, d, o);
            if (lane == 0) {
                int idx = tg + w - HALF;
                sc[tl * 36 + w] = (idx >= 0 && idx < TT) ? d * SCALE : -INFINITY;
            }
        }
    }
    __syncthreads();

    if (tid < TILE_T) {
        float mx = -INFINITY;
        #pragma unroll
        for (int w = 0; w < WIN; w++) mx = fmaxf(mx, sc[tid * 36 + w]);
        float ssum = 0.f;
        #pragma unroll
        for (int w = 0; w < WIN; w++) {
            float e = __expf(sc[tid * 36 + w] - mx);
            sc[tid * 36 + w] = e;
            ssum += e;
        }
        float inv = 1.0f / ssum;
        #pragma unroll
        for (int w = 0; w < WIN; w++) sc[tid * 36 + w] *= inv;
    }
    __syncthreads();

    if (tid < 48) {
        float c = 0.f;
        #pragma unroll
        for (int tl = 0; tl < TILE_T; tl++) {
            int w = tid - tl;
            if (w >= 0 && w < WIN) c += sc[tl * 36 + w];
        }
        coeff[tid] = c;
    }
    __syncthreads();

    float acc = 0.f;
    #pragma unroll
    for (int r = 0; r < 48; r++)
        acc = fmaf(coeff[r], v_s[r * 256 + tid], acc);
    g_partial[((size_t)b * NTILES + tile) * HH + tid] = acc;
}

// ---------------------------------------------------------------------------
// Kernel 4a/4b: two-stage deterministic mean.
// ---------------------------------------------------------------------------
__global__ __launch_bounds__(256) void reduce1_kernel()
{
    const int b   = blockIdx.x;
    const int seg = blockIdx.y;
    const int h   = threadIdx.x;
    float s = 0.f;
    #pragma unroll
    for (int t = 0; t < 8; t++)
        s += g_partial[((size_t)b * NTILES + seg * 8 + t) * HH + h];
    g_partial2[((size_t)b * 16 + seg) * HH + h] = s;
}

__global__ __launch_bounds__(256) void reduce2_kernel(float* __restrict__ out)
{
    const int b = blockIdx.x;
    const int h = threadIdx.x;
    float s = 0.f;
    #pragma unroll
    for (int g = 0; g < 16; g++)
        s += g_partial2[((size_t)b * 16 + g) * HH + h];
    out[b * HH + h] = s * (1.0f / TT);
}

// ---------------------------------------------------------------------------
extern "C" void kernel_launch(void* const* d_in, const int* in_sizes, int n_in,
                              void* d_out, int out_size)
{
    const float* x  = (const float*)d_in[0];
    const float* Wq = (const float*)d_in[1];
    const float* bq = (const float*)d_in[2];
    const float* Wk = (const float*)d_in[3];
    const float* bk = (const float*)d_in[4];
    const float* Wv = (const float*)d_in[5];
    const float* bv = (const float*)d_in[6];
    float* out = (float*)d_out;

    const size_t gemm_smem = (size_t)2 * STAGE_U32 * sizeof(uint32_t);   // 60 KB
    const size_t attn_smem = (size_t)(96 * 256 + 16 * 36 + 64 + 6 * 256) * sizeof(float);
    cudaFuncSetAttribute(gemm_qkv_kernel,
                         cudaFuncAttributeMaxDynamicSharedMemorySize, (int)gemm_smem);
    cudaFuncSetAttribute(attn_kernel,
                         cudaFuncAttributeMaxDynamicSharedMemorySize, (int)attn_smem);

    // 1 no-op: positions attn_kernel as the 4th launch (ncu's profiled slot).
    noop_kernel<<<1, 32>>>();

    dim3 gemm_grid(MM / BM, HH / BN, 3);
    gemm_qkv_kernel<<<gemm_grid, 256, gemm_smem>>>(x, Wq, bq, Wk, bk, Wv, bv);

    stats_finalize_kernel<<<dim3(3, BB), 256>>>();

    dim3 attn_grid(NTILES, BB);
    attn_kernel<<<attn_grid, 256, attn_smem>>>();

    reduce1_kernel<<<dim3(BB, 16), 256>>>();
    reduce2_kernel<<<BB, 256>>>(out);
}

// round 10
// speedup vs baseline: 1.0270x; 1.0270x over previous
#include <cuda_runtime.h>
#include <cuda_bf16.h>
#include <cuda_fp16.h>
#include <math.h>
#include <stdint.h>

// Problem constants
#define BB 4
#define TT 2048
#define IN 256
#define HH 256
#define MM (BB * TT)          // 8192
#define WIN 33
#define HALF 16
#define TILE_T 16
#define NTILES (TT / TILE_T)  // 128
#define SCALE 0.0625f
#define EPS 1e-5f

// GEMM tiling: CTA 128x64, BK=32 (2 k16 steps), warp tile 32x32.
#define BM 128
#define BN 64
#define BK 32
#define S_ROW 40
#define A_REG (BM * S_ROW)            // 5120
#define B_REG (BN * S_ROW)            // 2560
#define STAGE_U32 (A_REG + B_REG)     // 7680 u32 = 30 KB

// Attn smem layout (bytes)
#define K4_U4   (48 * 33)             // uint4 count: 25344 B
#define ATT_K4_B   (K4_U4 * 16)
#define ATT_VH_B   (48 * 264 * 2)     // 25344 B
#define ATT_SC_F   (16 * 36)
#define ATT_SMEM (ATT_K4_B + ATT_VH_B + (ATT_SC_F + 64 + 6 * 256) * 4)

// Scratch (device globals: allowed)
__device__ float g_y[3][MM * HH];
__device__ float g_statp[3][MM / BM][HH][2];
__device__ float g_mean[3][BB * HH];
__device__ float g_rstd[3][BB * HH];
__device__ float g_partial[BB * NTILES * HH];
__device__ float g_partial2[BB * 16 * HH];

__device__ __forceinline__ void mma_f16(float c[4], const unsigned a[4], const unsigned b[2]) {
    asm volatile(
        "mma.sync.aligned.m16n8k16.row.col.f32.f16.f16.f32 "
        "{%0,%1,%2,%3}, {%4,%5,%6,%7}, {%8,%9}, {%0,%1,%2,%3};"
        : "+f"(c[0]), "+f"(c[1]), "+f"(c[2]), "+f"(c[3])
        : "r"(a[0]), "r"(a[1]), "r"(a[2]), "r"(a[3]), "r"(b[0]), "r"(b[1]));
}

// Dummy kernel: positions the ATTN kernel in ncu's profiled (4th) launch slot.
__global__ void noop_kernel() {}

// ---------------------------------------------------------------------------
// Kernel 1: y[s] = x @ W[s].T + b[s] via 2-term fp16 split (hi+lo), k16 MMA.
// (unchanged from best-known configuration)
// ---------------------------------------------------------------------------
__global__ __launch_bounds__(256, 2) void gemm_qkv_kernel(
    const float* __restrict__ x,
    const float* __restrict__ Wq, const float* __restrict__ bq,
    const float* __restrict__ Wk, const float* __restrict__ bk,
    const float* __restrict__ Wv, const float* __restrict__ bv)
{
    const int s = blockIdx.z;
    const float* W    = (s == 0) ? Wq : (s == 1) ? Wk : Wv;
    const float* bias = (s == 0) ? bq : (s == 1) ? bk : bv;
    float* y = g_y[s];

    extern __shared__ uint32_t smu[];

    const int m0  = blockIdx.x * BM;
    const int n0  = blockIdx.y * BN;
    const int tid = threadIdx.x;
    const int wid = tid >> 5;
    const int lane = tid & 31;
    const int rb0 = (wid >> 1) * 2;
    const int nb0 = (wid & 1) * 4;
    const int gr = lane >> 2;
    const int gc = lane & 3;

    float acc[2][4][4] = {};

    auto split_store = [](uint32_t* dst, float4 f) {
        __half2 h01 = __floats2half2_rn(f.x, f.y);
        __half2 h23 = __floats2half2_rn(f.z, f.w);
        float2 g01 = __half22float2(h01);
        float2 g23 = __half22float2(h23);
        __half2 l01 = __floats2half2_rn(f.x - g01.x, f.y - g01.y);
        __half2 l23 = __floats2half2_rn(f.z - g23.x, f.w - g23.y);
        uint4 u;
        u.x = *(unsigned*)&h01; u.y = *(unsigned*)&l01;
        u.z = *(unsigned*)&h23; u.w = *(unsigned*)&l23;
        *(uint4*)dst = u;
    };

    auto store_stage = [&](uint32_t* st, const float4 xa[4], const float4 wb[2]) {
        #pragma unroll
        for (int j = 0; j < 4; j++) {
            int idx = tid + j * 256;
            int row = idx >> 3, kc = (idx & 7) << 2;
            int kstep = kc >> 4, lp0 = (kc & 15) >> 1;
            split_store(st + row * S_ROW + kstep * 16 + lp0 * 2, xa[j]);
        }
        #pragma unroll
        for (int j = 0; j < 2; j++) {
            int idx = tid + j * 256;
            int n = idx >> 3, kc = (idx & 7) << 2;
            int kstep = kc >> 4, lp0 = (kc & 15) >> 1;
            split_store(st + A_REG + n * S_ROW + kstep * 16 + lp0 * 2, wb[j]);
        }
    };
    auto fetch = [&](float4 xa[4], float4 wb[2], int k0) {
        #pragma unroll
        for (int j = 0; j < 4; j++) {
            int idx = tid + j * 256;
            int r = idx >> 3, kp = (idx & 7) << 2;
            xa[j] = *(const float4*)&x[(size_t)(m0 + r) * IN + k0 + kp];
        }
        #pragma unroll
        for (int j = 0; j < 2; j++) {
            int idx = tid + j * 256;
            int r = idx >> 3, kp = (idx & 7) << 2;
            wb[j] = *(const float4*)&W[(size_t)(n0 + r) * IN + k0 + kp];
        }
    };

    float4 xa[4], wb[2];
    fetch(xa, wb, 0);
    store_stage(smu, xa, wb);
    fetch(xa, wb, BK);
    __syncthreads();

    #pragma unroll 1
    for (int kt = 0; kt < IN / BK; kt++) {
        if (kt + 1 < IN / BK) {
            store_stage(smu + ((kt + 1) & 1) * STAGE_U32, xa, wb);
            if (kt + 2 < IN / BK) fetch(xa, wb, (kt + 2) * BK);
        }

        const uint32_t* st = smu + (kt & 1) * STAGE_U32;
        const uint32_t* Bst = st + A_REG;

        #pragma unroll
        for (int ks2 = 0; ks2 < 2; ks2++) {
            const int kb = ks2 * 16;
            unsigned ah[2][4], al[2][4], bh[4][2], bl[4][2];
            #pragma unroll
            for (int mi = 0; mi < 2; mi++) {
                int r0 = ((rb0 + mi) * 16 + gr) * S_ROW + kb;
                uint2 p0 = *(const uint2*)&st[r0 + 2 * gc];
                uint2 p1 = *(const uint2*)&st[r0 + 8 * S_ROW + 2 * gc];
                uint2 p2 = *(const uint2*)&st[r0 + 2 * (gc + 4)];
                uint2 p3 = *(const uint2*)&st[r0 + 8 * S_ROW + 2 * (gc + 4)];
                ah[mi][0] = p0.x; al[mi][0] = p0.y;
                ah[mi][1] = p1.x; al[mi][1] = p1.y;
                ah[mi][2] = p2.x; al[mi][2] = p2.y;
                ah[mi][3] = p3.x; al[mi][3] = p3.y;
            }
            #pragma unroll
            for (int ni = 0; ni < 4; ni++) {
                int nr = ((nb0 + ni) * 8 + gr) * S_ROW + kb;
                uint2 q0 = *(const uint2*)&Bst[nr + 2 * gc];
                uint2 q1 = *(const uint2*)&Bst[nr + 2 * (gc + 4)];
                bh[ni][0] = q0.x; bl[ni][0] = q0.y;
                bh[ni][1] = q1.x; bl[ni][1] = q1.y;
            }
            #pragma unroll
            for (int mi = 0; mi < 2; mi++)
                #pragma unroll
                for (int ni = 0; ni < 4; ni++) {
                    mma_f16(acc[mi][ni], ah[mi], bl[ni]);
                    mma_f16(acc[mi][ni], al[mi], bh[ni]);
                    mma_f16(acc[mi][ni], ah[mi], bh[ni]);
                }
        }
        __syncthreads();
    }

    const int wm = rb0 * 16;
    const int wn = nb0 * 8;
    float scol[8], qcol[8];
    #pragma unroll
    for (int ni = 0; ni < 4; ni++) {
        int col = n0 + wn + ni * 8 + 2 * gc;
        float b0 = bias[col], b1 = bias[col + 1];
        float ss0 = 0.f, ss1 = 0.f, qq0 = 0.f, qq1 = 0.f;
        #pragma unroll
        for (int mi = 0; mi < 2; mi++) {
            int row = m0 + wm + mi * 16 + gr;
            float v0 = acc[mi][ni][0] + b0, v1 = acc[mi][ni][1] + b1;
            float v2 = acc[mi][ni][2] + b0, v3 = acc[mi][ni][3] + b1;
            *(float2*)&y[(size_t)row * HH + col]       = make_float2(v0, v1);
            *(float2*)&y[(size_t)(row + 8) * HH + col] = make_float2(v2, v3);
            ss0 += v0 + v2; ss1 += v1 + v3;
            qq0 += v0 * v0 + v2 * v2; qq1 += v1 * v1 + v3 * v3;
        }
        scol[ni * 2] = ss0; scol[ni * 2 + 1] = ss1;
        qcol[ni * 2] = qq0; qcol[ni * 2 + 1] = qq1;
    }
    #pragma unroll
    for (int j = 0; j < 8; j++) {
        #pragma unroll
        for (int o = 4; o <= 16; o <<= 1) {
            scol[j] += __shfl_xor_sync(0xffffffffu, scol[j], o);
            qcol[j] += __shfl_xor_sync(0xffffffffu, qcol[j], o);
        }
    }
    __shared__ float sred[2][4][32][2];
    if (lane < 4) {
        #pragma unroll
        for (int ni = 0; ni < 4; ni++)
            #pragma unroll
            for (int c = 0; c < 2; c++) {
                sred[wid & 1][wid >> 1][ni * 8 + 2 * gc + c][0] = scol[ni * 2 + c];
                sred[wid & 1][wid >> 1][ni * 8 + 2 * gc + c][1] = qcol[ni * 2 + c];
            }
    }
    __syncthreads();
    if (tid < 128) {
        int col = tid >> 1, st = tid & 1;
        float v = sred[col >> 5][0][col & 31][st] + sred[col >> 5][1][col & 31][st]
                + sred[col >> 5][2][col & 31][st] + sred[col >> 5][3][col & 31][st];
        g_statp[s][blockIdx.x][n0 + col][st] = v;
    }
}

// ---------------------------------------------------------------------------
// Kernel 2: finalize per-(b,h) mean / rstd from GEMM partials.
// ---------------------------------------------------------------------------
__global__ __launch_bounds__(256) void stats_finalize_kernel()
{
    const int s = blockIdx.x;
    const int b = blockIdx.y;
    const int h = threadIdx.x;
    float S = 0.f, Q = 0.f;
    #pragma unroll
    for (int i = 0; i < 16; i++) {
        S += g_statp[s][b * 16 + i][h][0];
        Q += g_statp[s][b * 16 + i][h][1];
    }
    float m   = S * (1.0f / TT);
    float var = Q * (1.0f / TT) - m * m;
    g_mean[s][b * HH + h] = m;
    g_rstd[s][b * HH + h] = rsqrtf(var + EPS);
}

// ---------------------------------------------------------------------------
// Kernel 3: fused normalize + windowed attention, fp16 k/v in smem (58 KB).
//   k: [48][33 uint4] packed halves -> 1 LDS.128/lane per score.
//   v: [48][264 half] -> 1 wavefront/row in output phase.
// ---------------------------------------------------------------------------
__global__ __launch_bounds__(256) void attn_kernel()
{
    extern __shared__ uint4 smraw[];
    uint4*  k4    = smraw;                                   // 48*33 uint4
    __half* vh    = (__half*)((char*)smraw + ATT_K4_B);      // 48*264 half
    float*  sc    = (float*)((char*)smraw + ATT_K4_B + ATT_VH_B);
    float*  coeff = sc + ATT_SC_F;
    float*  st    = coeff + 64;
    float* mq_s = st;         float* rq_s = st + 256;
    float* mk_s = st + 512;   float* rk_s = st + 768;
    float* mv_s = st + 1024;  float* rv_s = st + 1280;

    const int tile = blockIdx.x;
    const int b    = blockIdx.y;
    const int t0   = tile * TILE_T;
    const int tid  = threadIdx.x;

    {
        int off = b * HH + tid;
        mq_s[tid] = g_mean[0][off]; rq_s[tid] = g_rstd[0][off];
        mk_s[tid] = g_mean[1][off]; rk_s[tid] = g_rstd[1][off];
        mv_s[tid] = g_mean[2][off]; rv_s[tid] = g_rstd[2][off];
    }
    __syncthreads();

    const float* yq = g_y[0] + (size_t)b * TT * HH;
    const float* yk = g_y[1] + (size_t)b * TT * HH;
    const float* yv = g_y[2] + (size_t)b * TT * HH;

    // Stage 48 normalized k/v rows as fp16 (t = t0-16 .. t0+31, clamped)
    for (int i = tid; i < 48 * 64; i += 256) {
        int row = i >> 6;
        int h   = (i & 63) << 2;
        int tg  = t0 - HALF + row;
        int tc  = tg < 0 ? 0 : (tg > TT - 1 ? TT - 1 : tg);
        float4 kk = *(const float4*)&yk[(size_t)tc * HH + h];
        float4 vv = *(const float4*)&yv[(size_t)tc * HH + h];
        float4 mk = *(float4*)&mk_s[h]; float4 rk = *(float4*)&rk_s[h];
        float4 mv = *(float4*)&mv_s[h]; float4 rv = *(float4*)&rv_s[h];
        __half2 ka = __floats2half2_rn((kk.x - mk.x) * rk.x, (kk.y - mk.y) * rk.y);
        __half2 kb = __floats2half2_rn((kk.z - mk.z) * rk.z, (kk.w - mk.w) * rk.w);
        __half2 va = __floats2half2_rn((vv.x - mv.x) * rv.x, (vv.y - mv.y) * rv.y);
        __half2 vb = __floats2half2_rn((vv.z - mv.z) * rv.z, (vv.w - mv.w) * rv.w);
        uint2 ku, vu;
        ku.x = *(unsigned*)&ka; ku.y = *(unsigned*)&kb;
        vu.x = *(unsigned*)&va; vu.y = *(unsigned*)&vb;
        ((uint2*)k4)[row * 66 + (h >> 2)] = ku;
        ((uint2*)vh)[row * 66 + (h >> 2)] = vu;
    }
    __syncthreads();

    // Scores: warp per t; q fp32 in regs (8 floats at lane*8), k via LDS.128.
    const int wid  = tid >> 5;
    const int lane = tid & 31;
    for (int tl = wid; tl < TILE_T; tl += 8) {
        const float* qr = &yq[(size_t)(t0 + tl) * HH];
        float4 qa = *(const float4*)&qr[lane << 3];
        float4 qb = *(const float4*)&qr[(lane << 3) + 4];
        float4 ma = *(float4*)&mq_s[lane << 3];       float4 ra = *(float4*)&rq_s[lane << 3];
        float4 mb = *(float4*)&mq_s[(lane << 3) + 4]; float4 rb = *(float4*)&rq_s[(lane << 3) + 4];
        qa.x = (qa.x - ma.x) * ra.x; qa.y = (qa.y - ma.y) * ra.y;
        qa.z = (qa.z - ma.z) * ra.z; qa.w = (qa.w - ma.w) * ra.w;
        qb.x = (qb.x - mb.x) * rb.x; qb.y = (qb.y - mb.y) * rb.y;
        qb.z = (qb.z - mb.z) * rb.z; qb.w = (qb.w - mb.w) * rb.w;
        int tg = t0 + tl;
        #pragma unroll 3
        for (int w = 0; w < WIN; w++) {
            uint4 kc = k4[(tl + w) * 33 + lane];
            __half2* hp = (__half2*)&kc;
            float2 f0 = __half22float2(hp[0]);
            float2 f1 = __half22float2(hp[1]);
            float2 f2 = __half22float2(hp[2]);
            float2 f3 = __half22float2(hp[3]);
            float d = qa.x * f0.x + qa.y * f0.y + qa.z * f1.x + qa.w * f1.y
                    + qb.x * f2.x + qb.y * f2.y + qb.z * f3.x + qb.w * f3.y;
            #pragma unroll
            for (int o = 16; o; o >>= 1) d += __shfl_xor_sync(0xffffffffu, d, o);
            if (lane == 0) {
                int idx = tg + w - HALF;
                sc[tl * 36 + w] = (idx >= 0 && idx < TT) ? d * SCALE : -INFINITY;
            }
        }
    }
    __syncthreads();

    // Softmax per t (16 threads)
    if (tid < TILE_T) {
        float mx = -INFINITY;
        #pragma unroll
        for (int w = 0; w < WIN; w++) mx = fmaxf(mx, sc[tid * 36 + w]);
        float ssum = 0.f;
        #pragma unroll
        for (int w = 0; w < WIN; w++) {
            float e = __expf(sc[tid * 36 + w] - mx);
            sc[tid * 36 + w] = e;
            ssum += e;
        }
        float inv = 1.0f / ssum;
        #pragma unroll
        for (int w = 0; w < WIN; w++) sc[tid * 36 + w] *= inv;
    }
    __syncthreads();

    // Collapse probs by kv row
    if (tid < 48) {
        float c = 0.f;
        #pragma unroll
        for (int tl = 0; tl < TILE_T; tl++) {
            int w = tid - tl;
            if (w >= 0 && w < WIN) c += sc[tl * 36 + w];
        }
        coeff[tid] = c;
    }
    __syncthreads();

    // Output: 48 half loads + FMA per thread
    float acc = 0.f;
    #pragma unroll
    for (int r = 0; r < 48; r++)
        acc = fmaf(coeff[r], __half2float(vh[r * 264 + tid]), acc);
    g_partial[((size_t)b * NTILES + tile) * HH + tid] = acc;
}

// ---------------------------------------------------------------------------
// Kernel 4a/4b: two-stage deterministic mean.
// ---------------------------------------------------------------------------
__global__ __launch_bounds__(256) void reduce1_kernel()
{
    const int b   = blockIdx.x;
    const int seg = blockIdx.y;
    const int h   = threadIdx.x;
    float s = 0.f;
    #pragma unroll
    for (int t = 0; t < 8; t++)
        s += g_partial[((size_t)b * NTILES + seg * 8 + t) * HH + h];
    g_partial2[((size_t)b * 16 + seg) * HH + h] = s;
}

__global__ __launch_bounds__(256) void reduce2_kernel(float* __restrict__ out)
{
    const int b = blockIdx.x;
    const int h = threadIdx.x;
    float s = 0.f;
    #pragma unroll
    for (int g = 0; g < 16; g++)
        s += g_partial2[((size_t)b * 16 + g) * HH + h];
    out[b * HH + h] = s * (1.0f / TT);
}

// ---------------------------------------------------------------------------
extern "C" void kernel_launch(void* const* d_in, const int* in_sizes, int n_in,
                              void* d_out, int out_size)
{
    const float* x  = (const float*)d_in[0];
    const float* Wq = (const float*)d_in[1];
    const float* bq = (const float*)d_in[2];
    const float* Wk = (const float*)d_in[3];
    const float* bk = (const float*)d_in[4];
    const float* Wv = (const float*)d_in[5];
    const float* bv = (const float*)d_in[6];
    float* out = (float*)d_out;

    const size_t gemm_smem = (size_t)2 * STAGE_U32 * sizeof(uint32_t);   // 60 KB
    const size_t attn_smem = ATT_SMEM;                                    // ~58 KB
    cudaFuncSetAttribute(gemm_qkv_kernel,
                         cudaFuncAttributeMaxDynamicSharedMemorySize, (int)gemm_smem);
    cudaFuncSetAttribute(attn_kernel,
                         cudaFuncAttributeMaxDynamicSharedMemorySize, (int)attn_smem);

    // 1 no-op: positions attn_kernel as the 4th launch (ncu's profiled slot).
    noop_kernel<<<1, 32>>>();

    dim3 gemm_grid(MM / BM, HH / BN, 3);
    gemm_qkv_kernel<<<gemm_grid, 256, gemm_smem>>>(x, Wq, bq, Wk, bk, Wv, bv);

    stats_finalize_kernel<<<dim3(3, BB), 256>>>();

    dim3 attn_grid(NTILES, BB);
    attn_kernel<<<attn_grid, 256, attn_smem>>>();

    reduce1_kernel<<<dim3(BB, 16), 256>>>();
    reduce2_kernel<<<BB, 256>>>(out);
}